// round 8
// baseline (speedup 1.0000x reference)
#include <cuda_runtime.h>
#include <cuda_fp16.h>
#include <cstdint>

#define S        4096
#define D_IN     128
#define H        4
#define D        32
#define HD       128
#define KSPLIT   2
#define KEYS_PER_SPLIT (S / KSPLIT)   // 2048
#define KT       128                   // keys per smem tile
#define QT       128                   // queries per attention block (8 warps * 16)
#define NEGBIG   1e30f
#define QSCALE   (0.17677669529663687f * 1.4426950408889634f)  // scale*log2e

#define V_CHSTR  264                   // dwords per 16-key V chunk (256 + 8 pad)

// ---------------- scratch (fp16x2 packed, 16 dwords per row) ----------------
__device__ uint32_t g_q[H * S * 16];        // permuted cols, pre-scaled by QSCALE
__device__ uint32_t g_k[H * S * 16];        // permuted cols
__device__ uint32_t g_v[H * S * 16];        // plain d-pair packing
__device__ float g_pl[H * S * KSPLIT];
__device__ float g_po[H * S * KSPLIT * D];

// ---------------- helpers ----------------------------------------------------
__device__ __forceinline__ float2 ffma2(float2 a, float2 b, float2 c) {
    float2 r;
    asm("fma.rn.f32x2 %0, %1, %2, %3;"
        : "=l"(*reinterpret_cast<unsigned long long*>(&r))
        : "l"(*reinterpret_cast<unsigned long long*>(&a)),
          "l"(*reinterpret_cast<unsigned long long*>(&b)),
          "l"(*reinterpret_cast<unsigned long long*>(&c)));
    return r;
}
__device__ __forceinline__ float ex2(float x) {
    float r;
    asm("ex2.approx.f32 %0, %1;" : "=f"(r) : "f"(x));
    return r;
}
__device__ __forceinline__ uint32_t pack_h2(float lo, float hi) {
    __half2 h = __floats2half2_rn(lo, hi);       // x = lo bits, y = hi bits
    return *reinterpret_cast<uint32_t*>(&h);
}
__device__ __forceinline__ void mma16(float* d,
                                      uint32_t a0, uint32_t a1, uint32_t a2, uint32_t a3,
                                      uint32_t b0, uint32_t b1) {
    asm("mma.sync.aligned.m16n8k16.row.col.f32.f16.f16.f32 "
        "{%0,%1,%2,%3}, {%4,%5,%6,%7}, {%8,%9}, {%0,%1,%2,%3};"
        : "+f"(d[0]), "+f"(d[1]), "+f"(d[2]), "+f"(d[3])
        : "r"(a0), "r"(a1), "r"(a2), "r"(a3), "r"(b0), "r"(b1));
}

// ---------------- kernel 1: fused QKV projection (fp16 pack epilogue) -------
__global__ __launch_bounds__(256) void proj_kernel(
    const float* __restrict__ x,
    const float* __restrict__ Wq, const float* __restrict__ bq,
    const float* __restrict__ Wk, const float* __restrict__ bk,
    const float* __restrict__ Wv, const float* __restrict__ bv) {

    const int rowbase = blockIdx.x * 32;
    const int proj = blockIdx.y;
    const float* W    = (proj == 0) ? Wq : (proj == 1) ? Wk : Wv;
    const float* bias = (proj == 0) ? bq : (proj == 1) ? bk : bv;
    uint32_t* out     = (proj == 0) ? g_q : (proj == 1) ? g_k : g_v;

    __shared__ float sx[32 * D_IN];
    __shared__ float sw[32 * HD];

    const int tid = threadIdx.x;
    {
        const float4* xg = (const float4*)(x + (size_t)rowbase * D_IN);
        float4* sx4 = (float4*)sx;
        #pragma unroll
        for (int i = 0; i < 4; i++) sx4[tid + i * 256] = xg[tid + i * 256];
    }

    const int ty = tid >> 4;
    const int tx = tid & 15;

    float2 acc[2][4];
    #pragma unroll
    for (int r = 0; r < 2; r++)
        #pragma unroll
        for (int c = 0; c < 4; c++) acc[r][c] = make_float2(0.f, 0.f);

    for (int kk = 0; kk < 4; kk++) {
        __syncthreads();
        {
            const float4* wg = (const float4*)(W + (size_t)(kk * 32) * HD);
            float4* sw4 = (float4*)sw;
            #pragma unroll
            for (int i = 0; i < 4; i++) sw4[tid + i * 256] = wg[tid + i * 256];
        }
        __syncthreads();
        #pragma unroll
        for (int k = 0; k < 32; k++) {
            float x0s = sx[(ty * 2 + 0) * D_IN + kk * 32 + k];
            float x1s = sx[(ty * 2 + 1) * D_IN + kk * 32 + k];
            float2 x0 = make_float2(x0s, x0s);
            float2 x1 = make_float2(x1s, x1s);
            float4 w0 = *(const float4*)&sw[k * HD + tx * 8];
            float4 w1 = *(const float4*)&sw[k * HD + tx * 8 + 4];
            float2 wp[4] = {make_float2(w0.x, w0.y), make_float2(w0.z, w0.w),
                            make_float2(w1.x, w1.y), make_float2(w1.z, w1.w)};
            #pragma unroll
            for (int c = 0; c < 4; c++) {
                acc[0][c] = ffma2(x0, wp[c], acc[0][c]);
                acc[1][c] = ffma2(x1, wp[c], acc[1][c]);
            }
        }
    }

    const float oscale = (proj == 0) ? QSCALE : 1.0f;
    const bool permute = (proj != 2);   // Q and K get the MMA-fragment permutation
    #pragma unroll
    for (int r = 0; r < 2; r++) {
        int row = rowbase + ty * 2 + r;
        #pragma unroll
        for (int c = 0; c < 4; c++) {
            int col0 = tx * 8 + c * 2;
            float v0 = (acc[r][c].x + bias[col0])     * oscale;
            float v1 = (acc[r][c].y + bias[col0 + 1]) * oscale;
            int h0 = col0 >> 5;
            int d2 = (col0 & 31) >> 1;                 // d-pair index 0..15
            int p  = permute ? (((d2 & 3) << 2) | (d2 >> 2)) : d2;
            out[((size_t)h0 * S + row) * 16 + p] = pack_h2(v0, v1);
        }
    }
}

// ---------------- kernel 2: fp16 m16n8k16 flash attention -------------------
// grid (32, H, 2) = 256 blocks; 256 threads = 8 warps; 16 queries per warp.
__global__ __launch_bounds__(256, 3) void attn_kernel(const int* __restrict__ mask) {
    const int qtile = blockIdx.x;
    const int h     = blockIdx.y;
    const int kc    = blockIdx.z;
    const int tid   = threadIdx.x;
    const int warp  = tid >> 5;
    const int lane  = tid & 31;
    const int gid   = lane >> 2;
    const int tig   = lane & 3;

    __shared__ __align__(16) uint32_t sk[KT * 16];             // 8 KB (permuted fp16x2)
    __shared__ __align__(16) uint32_t sv[(KT / 16) * V_CHSTR]; // 8.25 KB
    __shared__ float sbias[KT];
    __shared__ int smask[64];

    if (tid < 64) smask[tid] = mask[tid];   // visible after first __syncthreads

    const int qbase = qtile * QT + warp * 16;

    // Q fragments: one LDG.128 per 8-row group (gmem pre-permuted).
    uint4 qlo, qhi;
    {
        const uint32_t* qr = g_q + ((size_t)(h * S) + qbase + gid) * 16;
        qlo = *(const uint4*)(qr + 4 * tig);
        qhi = *(const uint4*)(qr + 8 * 16 + 4 * tig);
    }

    float o[4][4];
    #pragma unroll
    for (int nc = 0; nc < 4; nc++)
        #pragma unroll
        for (int r = 0; r < 4; r++) o[nc][r] = 0.0f;
    float l0 = 0.0f, l1 = 0.0f;

    const int kbase = kc * KEYS_PER_SPLIT;
    const float2* sb2 = (const float2*)sbias;

    // V fill mapping: sv address(kp, d) = chunk*V_CHSTR + 8*d + 2*(kp&3) + (kp>>2)
    const int vkey2 = tid & 63;          // key-pair id within tile
    const int vdb   = tid >> 6;          // d-block 0..3 (8 d values each)
    const int vch   = vkey2 >> 3;
    const int vkc2  = vkey2 & 7;
    const int vwoff = vch * V_CHSTR + 64 * vdb + 2 * (vkc2 & 3) + (vkc2 >> 2);

    for (int jt = 0; jt < KEYS_PER_SPLIT / KT; jt++) {   // 16 tiles
        __syncthreads();
        {
            // K tile: straight copy (gmem already permuted)
            const uint4* kg4 = (const uint4*)(g_k + ((size_t)(h * S) + kbase + jt * KT) * 16);
            ((uint4*)sk)[tid]       = kg4[tid];
            ((uint4*)sk)[tid + 256] = kg4[tid + 256];

            // V tile: key-pair transpose via prmt (conflict-free STS, d-stride 8)
            const uint4* vg4 = (const uint4*)(g_v + ((size_t)(h * S) + kbase + jt * KT) * 16);
            uint4 e4 = vg4[(2 * vkey2) * 4 + vdb];
            uint4 o4 = vg4[(2 * vkey2) * 4 + 4 + vdb];
            uint32_t* dst = &sv[vwoff];
            dst[0]  = __byte_perm(e4.x, o4.x, 0x5410);
            dst[8]  = __byte_perm(e4.x, o4.x, 0x7632);
            dst[16] = __byte_perm(e4.y, o4.y, 0x5410);
            dst[24] = __byte_perm(e4.y, o4.y, 0x7632);
            dst[32] = __byte_perm(e4.z, o4.z, 0x5410);
            dst[40] = __byte_perm(e4.z, o4.z, 0x7632);
            dst[48] = __byte_perm(e4.w, o4.w, 0x5410);
            dst[56] = __byte_perm(e4.w, o4.w, 0x7632);

            if (tid < KT) {
                int key = kbase + jt * KT + tid;
                sbias[tid] = (smask[key >> 6] && smask[key & 63]) ? 0.0f : -NEGBIG;
            }
        }
        __syncthreads();

        #pragma unroll 1
        for (int kg = 0; kg < KT / 16; kg++) {     // 8 chunks of 16 keys
            // ---- K B-frags: one LDS.128 per 8-key group ----
            const uint4 kb0 = *(const uint4*)&sk[(kg * 16 + gid) * 16 + 4 * tig];
            const uint4 kb1 = *(const uint4*)&sk[(kg * 16 + 8 + gid) * 16 + 4 * tig];

            // ---- QK^T (fp32 accum) ----
            float c[2][4];
            #pragma unroll
            for (int g = 0; g < 2; g++)
                c[g][0] = c[g][1] = c[g][2] = c[g][3] = 0.0f;
            mma16(c[0], qlo.x, qhi.x, qlo.y, qhi.y, kb0.x, kb0.y);
            mma16(c[0], qlo.z, qhi.z, qlo.w, qhi.w, kb0.z, kb0.w);
            mma16(c[1], qlo.x, qhi.x, qlo.y, qhi.y, kb1.x, kb1.y);
            mma16(c[1], qlo.z, qhi.z, qlo.w, qhi.w, kb1.z, kb1.w);

            float2 bg0 = sb2[kg * 8 + tig];
            float2 bg1 = sb2[kg * 8 + 4 + tig];

            // ---- softmax numerators + scalar l accumulation (no ones-MMA) ----
            float p00 = ex2(c[0][0] + bg0.x), p01 = ex2(c[0][1] + bg0.y);
            float p02 = ex2(c[0][2] + bg0.x), p03 = ex2(c[0][3] + bg0.y);
            float p10 = ex2(c[1][0] + bg1.x), p11 = ex2(c[1][1] + bg1.y);
            float p12 = ex2(c[1][2] + bg1.x), p13 = ex2(c[1][3] + bg1.y);
            l0 += (p00 + p01) + (p10 + p11);
            l1 += (p02 + p03) + (p12 + p13);

            uint32_t pa0 = pack_h2(p00, p01);   // A[gid   ][k-pair tig]
            uint32_t pa1 = pack_h2(p02, p03);   // A[gid+8 ][k-pair tig]
            uint32_t pa2 = pack_h2(p10, p11);   // A[gid   ][k-pair tig+4]
            uint32_t pa3 = pack_h2(p12, p13);   // A[gid+8 ][k-pair tig+4]

            // ---- PV ----
            const uint32_t* vb = &sv[kg * V_CHSTR + 8 * gid + 2 * tig];
            #pragma unroll
            for (int nc = 0; nc < 4; nc++) {
                uint2 vv = *(const uint2*)(vb + 64 * nc);   // d-col = 8nc + gid
                mma16(o[nc], pa0, pa1, pa2, pa3, vv.x, vv.y);
            }
        }
    }

    // ---- reduce l across the 4 threads of each group; write partials ----
    const unsigned FULL = 0xffffffffu;
    l0 += __shfl_xor_sync(FULL, l0, 1); l0 += __shfl_xor_sync(FULL, l0, 2);
    l1 += __shfl_xor_sync(FULL, l1, 1); l1 += __shfl_xor_sync(FULL, l1, 2);

    const int q0 = qbase + gid;
    const int q1 = q0 + 8;
    const int prow0 = ((h * S) + q0) * KSPLIT + kc;
    const int prow1 = ((h * S) + q1) * KSPLIT + kc;
    if (tig == 0) {
        g_pl[prow0] = l0;
        g_pl[prow1] = l1;
    }
    float2* po0 = (float2*)(g_po + (size_t)prow0 * D);
    float2* po1 = (float2*)(g_po + (size_t)prow1 * D);
    #pragma unroll
    for (int nc = 0; nc < 4; nc++) {
        po0[nc * 4 + tig] = make_float2(o[nc][0], o[nc][1]);
        po1[nc * 4 + tig] = make_float2(o[nc][2], o[nc][3]);
    }
}

// ---------------- kernel 3: combine split-K + sum-pool over j ---------------
__global__ __launch_bounds__(128) void reduce_kernel(float* __restrict__ out) {
    const int i = blockIdx.x;
    const int h = blockIdx.y;
    const int tid = threadIdx.x;
    const int jg = tid >> 5;
    const int d  = tid & 31;

    __shared__ float sinvL[64];
    __shared__ float sacc[128];

    if (tid < 64) {
        int s = i * 64 + tid;
        int base = (h * S + s) * KSPLIT;
        float L = 0.0f;
        #pragma unroll
        for (int k = 0; k < KSPLIT; k++) L += g_pl[base + k];
        sinvL[tid] = 1.0f / L;
    }
    __syncthreads();

    float acc = 0.0f;
    #pragma unroll 4
    for (int jj = 0; jj < 16; jj++) {
        int j = jg * 16 + jj;
        int s = i * 64 + j;
        size_t base = ((size_t)(h * S + s) * KSPLIT) * D + d;
        float ov = 0.0f;
        #pragma unroll
        for (int k = 0; k < KSPLIT; k++) ov += g_po[base + (size_t)k * D];
        acc += ov * sinvL[j];
    }

    sacc[tid] = acc;
    __syncthreads();
    if (tid < 32) {
        float r = sacc[tid] + sacc[tid + 32] + sacc[tid + 64] + sacc[tid + 96];
        out[i * HD + h * 32 + tid] = r;
    }
}

// ---------------- launch ----------------------------------------------------
extern "C" void kernel_launch(void* const* d_in, const int* in_sizes, int n_in,
                              void* d_out, int out_size) {
    const float* x    = (const float*)d_in[0];
    const int*   mask = (const int*)  d_in[1];
    const float* Wq   = (const float*)d_in[2];
    const float* bq   = (const float*)d_in[3];
    const float* Wk   = (const float*)d_in[4];
    const float* bk   = (const float*)d_in[5];
    const float* Wv   = (const float*)d_in[6];
    const float* bv   = (const float*)d_in[7];
    float* out = (float*)d_out;

    proj_kernel<<<dim3(S / 32, 3), 256>>>(x, Wq, bq, Wk, bk, Wv, bv);
    attn_kernel<<<dim3(S / QT, H, KSPLIT), 256>>>(mask);
    reduce_kernel<<<dim3(64, H), 128>>>(out);
}

// round 9
// speedup vs baseline: 1.6737x; 1.6737x over previous
#include <cuda_runtime.h>
#include <cuda_fp16.h>
#include <cstdint>

#define S        4096
#define D_IN     128
#define H        4
#define D        32
#define HD       128
#define KSPLIT   4
#define KEYS_PER_SPLIT (S / KSPLIT)   // 1024
#define KT       128                   // keys per smem tile
#define QT       256                   // queries per attention block (8 warps * 32)
#define NEGBIG   1e30f
#define QSCALE   (0.17677669529663687f * 1.4426950408889634f)  // scale*log2e

#define V_CHSTR  264                   // dwords per 16-key V chunk (256 + 8 pad)
#define PROJ_SMEM ((2 * 128 * 64) * 4 + 512)

// ---------------- scratch (fp16x2 packed, 16 dwords per row) ----------------
__device__ uint32_t g_q[H * S * 16];        // permuted cols, pre-scaled by QSCALE
__device__ uint32_t g_k[H * S * 16];        // permuted cols
__device__ uint32_t g_v[H * S * 16];        // plain d-pair packing
__device__ float g_pl[H * S * KSPLIT];
__device__ float g_po[H * S * KSPLIT * D];

// ---------------- helpers ----------------------------------------------------
__device__ __forceinline__ float ex2(float x) {
    float r;
    asm("ex2.approx.f32 %0, %1;" : "=f"(r) : "f"(x));
    return r;
}
__device__ __forceinline__ uint32_t pack_h2(float lo, float hi) {
    __half2 h = __floats2half2_rn(lo, hi);       // x = lo bits, y = hi bits
    return *reinterpret_cast<uint32_t*>(&h);
}
__device__ __forceinline__ void mma16(float* d,
                                      uint32_t a0, uint32_t a1, uint32_t a2, uint32_t a3,
                                      uint32_t b0, uint32_t b1) {
    asm("mma.sync.aligned.m16n8k16.row.col.f32.f16.f16.f32 "
        "{%0,%1,%2,%3}, {%4,%5,%6,%7}, {%8,%9}, {%0,%1,%2,%3};"
        : "+f"(d[0]), "+f"(d[1]), "+f"(d[2]), "+f"(d[3])
        : "r"(a0), "r"(a1), "r"(a2), "r"(a3), "r"(b0), "r"(b1));
}
// group swizzle keyed on row (bit0 -> group bit2; bits1-2 -> group bits0-1)
__device__ __forceinline__ int swz3(int r) { return ((r & 1) << 2) | ((r >> 1) & 3); }

// ---------------- kernel 1: fp16 MMA QKV projection --------------------------
// grid (32 row-tiles, 3 proj); 256 threads = 8 warps; 16 rows per warp.
__global__ __launch_bounds__(256) void proj_kernel(
    const float* __restrict__ x,
    const float* __restrict__ Wq, const float* __restrict__ bq,
    const float* __restrict__ Wk, const float* __restrict__ bk,
    const float* __restrict__ Wv, const float* __restrict__ bv) {

    extern __shared__ uint32_t dsm[];
    uint32_t* sxh = dsm;                 // 128 rows x 64 pair-dwords (swizzled)
    uint32_t* swt = dsm + 128 * 64;      // W^T: 128 n-rows x 64 k-pair dwords
    float*    sb  = (float*)(dsm + 2 * 128 * 64);   // 128 bias

    const int rowbase = blockIdx.x * 128;
    const int proj = blockIdx.y;
    const float* W    = (proj == 0) ? Wq : (proj == 1) ? Wk : Wv;
    const float* bias = (proj == 0) ? bq : (proj == 1) ? bk : bv;
    uint32_t* out     = (proj == 0) ? g_q : (proj == 1) ? g_k : g_v;

    const int tid  = threadIdx.x;
    const int wid  = tid >> 5;
    const int lane = tid & 31;
    const int gid  = lane >> 2;
    const int tig  = lane & 3;

    // ---- fill x (fp32 -> fp16x2 pairs, swizzled) ----
    #pragma unroll 8
    for (int i = 0; i < 32; i++) {
        int e = tid + (i << 8);          // 8192 pairs
        int row = e >> 6, p = e & 63;
        float2 xv = *(const float2*)(x + (size_t)(rowbase + row) * D_IN + 2 * p);
        sxh[row * 64 + ((((p & 7) ^ swz3(row)) << 3) | (p >> 3))] = pack_h2(xv.x, xv.y);
    }
    // ---- fill W^T: swt[n][pair p] = {W[2p][n], W[2p+1][n]} ----
    {
        int n = tid & 127;
        int pbase = (tid >> 7) << 5;
        #pragma unroll 8
        for (int i = 0; i < 32; i++) {
            int p = pbase + i;
            float w0 = W[(size_t)(2 * p)     * HD + n];
            float w1 = W[(size_t)(2 * p + 1) * HD + n];
            swt[n * 64 + ((((p & 7) ^ swz3(n)) << 3) | (p >> 3))] = pack_h2(w0, w1);
        }
    }
    if (tid < 128) sb[tid] = bias[tid];
    __syncthreads();

    // ---- A fragments (rows r0, r1 held for all 16 n-blocks) ----
    const int r0 = (wid << 4) + gid;
    const int r1 = r0 + 8;
    uint32_t a0[8], a1[8], a2[8], a3[8];
    {
        const uint32_t* x0 = &sxh[r0 * 64];
        const uint32_t* x1 = &sxh[r1 * 64];
        int g0 = ((tig)     ^ swz3(r0)) << 3;
        int g2 = ((tig + 4) ^ swz3(r0)) << 3;
        int h0 = ((tig)     ^ swz3(r1)) << 3;
        int h2 = ((tig + 4) ^ swz3(r1)) << 3;
        *(uint4*)&a0[0] = *(const uint4*)&x0[g0]; *(uint4*)&a0[4] = *(const uint4*)&x0[g0 + 4];
        *(uint4*)&a2[0] = *(const uint4*)&x0[g2]; *(uint4*)&a2[4] = *(const uint4*)&x0[g2 + 4];
        *(uint4*)&a1[0] = *(const uint4*)&x1[h0]; *(uint4*)&a1[4] = *(const uint4*)&x1[h0 + 4];
        *(uint4*)&a3[0] = *(const uint4*)&x1[h2]; *(uint4*)&a3[4] = *(const uint4*)&x1[h2 + 4];
    }

    const float oscale = (proj == 0) ? QSCALE : 1.0f;
    const bool permute = (proj != 2);

    // ---- 16 n-blocks, 2 at a time for MMA ILP ----
    #pragma unroll 1
    for (int nb2 = 0; nb2 < 8; nb2++) {
        const int nbA = 2 * nb2, nbB = 2 * nb2 + 1;
        const int nA = nbA * 8 + gid, nB = nbB * 8 + gid;

        uint32_t b0A[8], b1A[8], b0B[8], b1B[8];
        {
            const uint32_t* wA = &swt[nA * 64];
            int ga = ((tig)     ^ swz3(nA)) << 3;
            int gb = ((tig + 4) ^ swz3(nA)) << 3;
            *(uint4*)&b0A[0] = *(const uint4*)&wA[ga]; *(uint4*)&b0A[4] = *(const uint4*)&wA[ga + 4];
            *(uint4*)&b1A[0] = *(const uint4*)&wA[gb]; *(uint4*)&b1A[4] = *(const uint4*)&wA[gb + 4];
            const uint32_t* wB = &swt[nB * 64];
            int gc = ((tig)     ^ swz3(nB)) << 3;
            int gd = ((tig + 4) ^ swz3(nB)) << 3;
            *(uint4*)&b0B[0] = *(const uint4*)&wB[gc]; *(uint4*)&b0B[4] = *(const uint4*)&wB[gc + 4];
            *(uint4*)&b1B[0] = *(const uint4*)&wB[gd]; *(uint4*)&b1B[4] = *(const uint4*)&wB[gd + 4];
        }

        float cA[4] = {0.f, 0.f, 0.f, 0.f};
        float cB[4] = {0.f, 0.f, 0.f, 0.f};
        #pragma unroll
        for (int ks = 0; ks < 8; ks++) {
            mma16(cA, a0[ks], a1[ks], a2[ks], a3[ks], b0A[ks], b1A[ks]);
            mma16(cB, a0[ks], a1[ks], a2[ks], a3[ks], b0B[ks], b1B[ks]);
        }

        // ---- epilogue for both n-blocks ----
        #pragma unroll
        for (int s = 0; s < 2; s++) {
            const float* c = s ? cB : cA;
            const int nb = s ? nbB : nbA;
            const int col0 = 8 * nb + 2 * tig;
            float v0 = (c[0] + sb[col0])     * oscale;   // row r0
            float v1 = (c[1] + sb[col0 + 1]) * oscale;
            float v2 = (c[2] + sb[col0])     * oscale;   // row r1
            float v3 = (c[3] + sb[col0 + 1]) * oscale;
            int h0 = col0 >> 5;
            int d2 = (col0 >> 1) & 15;
            int p  = permute ? (((d2 & 3) << 2) | (d2 >> 2)) : d2;
            out[((size_t)h0 * S + rowbase + r0) * 16 + p] = pack_h2(v0, v1);
            out[((size_t)h0 * S + rowbase + r1) * 16 + p] = pack_h2(v2, v3);
        }
    }
}

// ---------------- kernel 2: fp16 m16n8k16 flash attention -------------------
// grid (16, H, 4) = 256 blocks; 256 threads = 8 warps; 32 queries per warp.
__global__ __launch_bounds__(256, 2) void attn_kernel(const int* __restrict__ mask) {
    const int qtile = blockIdx.x;
    const int h     = blockIdx.y;
    const int kc    = blockIdx.z;
    const int tid   = threadIdx.x;
    const int warp  = tid >> 5;
    const int lane  = tid & 31;
    const int gid   = lane >> 2;
    const int tig   = lane & 3;

    __shared__ __align__(16) uint32_t sk[KT * 16];             // 8 KB (permuted fp16x2)
    __shared__ __align__(16) uint32_t sv[(KT / 16) * V_CHSTR]; // 8.25 KB
    __shared__ float sbias[KT];
    __shared__ int smask[64];

    if (tid < 64) smask[tid] = mask[tid];

    const int qbase = qtile * QT + warp * 32;

    uint4 qlo[2], qhi[2];
    #pragma unroll
    for (int t = 0; t < 2; t++) {
        const uint32_t* qr = g_q + ((size_t)(h * S) + qbase + t * 16 + gid) * 16;
        qlo[t] = *(const uint4*)(qr + 4 * tig);
        qhi[t] = *(const uint4*)(qr + 8 * 16 + 4 * tig);
    }

    float o[2][4][4];
    #pragma unroll
    for (int t = 0; t < 2; t++)
        #pragma unroll
        for (int nc = 0; nc < 4; nc++)
            #pragma unroll
            for (int r = 0; r < 4; r++) o[t][nc][r] = 0.0f;
    float l[2][2] = {{0.f, 0.f}, {0.f, 0.f}};

    const int kbase = kc * KEYS_PER_SPLIT;
    const float2* sb2 = (const float2*)sbias;

    const int vkey2 = tid & 63;
    const int vdb   = tid >> 6;
    const int vch   = vkey2 >> 3;
    const int vkc2  = vkey2 & 7;
    const int vwoff = vch * V_CHSTR + 64 * vdb + 2 * (vkc2 & 3) + (vkc2 >> 2);

    for (int jt = 0; jt < KEYS_PER_SPLIT / KT; jt++) {   // 8 tiles
        __syncthreads();
        {
            const uint4* kg4 = (const uint4*)(g_k + ((size_t)(h * S) + kbase + jt * KT) * 16);
            ((uint4*)sk)[tid]       = kg4[tid];
            ((uint4*)sk)[tid + 256] = kg4[tid + 256];

            const uint4* vg4 = (const uint4*)(g_v + ((size_t)(h * S) + kbase + jt * KT) * 16);
            uint4 e4 = vg4[(2 * vkey2) * 4 + vdb];
            uint4 o4 = vg4[(2 * vkey2) * 4 + 4 + vdb];
            uint32_t* dst = &sv[vwoff];
            dst[0]  = __byte_perm(e4.x, o4.x, 0x5410);
            dst[8]  = __byte_perm(e4.x, o4.x, 0x7632);
            dst[16] = __byte_perm(e4.y, o4.y, 0x5410);
            dst[24] = __byte_perm(e4.y, o4.y, 0x7632);
            dst[32] = __byte_perm(e4.z, o4.z, 0x5410);
            dst[40] = __byte_perm(e4.z, o4.z, 0x7632);
            dst[48] = __byte_perm(e4.w, o4.w, 0x5410);
            dst[56] = __byte_perm(e4.w, o4.w, 0x7632);

            if (tid < KT) {
                int key = kbase + jt * KT + tid;
                sbias[tid] = (smask[key >> 6] && smask[key & 63]) ? 0.0f : -NEGBIG;
            }
        }
        __syncthreads();

        #pragma unroll 1
        for (int kg = 0; kg < KT / 16; kg++) {     // 8 chunks of 16 keys
            const uint4 kb0 = *(const uint4*)&sk[(kg * 16 + gid) * 16 + 4 * tig];
            const uint4 kb1 = *(const uint4*)&sk[(kg * 16 + 8 + gid) * 16 + 4 * tig];

            float c[2][2][4];
            #pragma unroll
            for (int t = 0; t < 2; t++) {
                #pragma unroll
                for (int g = 0; g < 2; g++)
                    c[t][g][0] = c[t][g][1] = c[t][g][2] = c[t][g][3] = 0.0f;
                mma16(c[t][0], qlo[t].x, qhi[t].x, qlo[t].y, qhi[t].y, kb0.x, kb0.y);
                mma16(c[t][0], qlo[t].z, qhi[t].z, qlo[t].w, qhi[t].w, kb0.z, kb0.w);
                mma16(c[t][1], qlo[t].x, qhi[t].x, qlo[t].y, qhi[t].y, kb1.x, kb1.y);
                mma16(c[t][1], qlo[t].z, qhi[t].z, qlo[t].w, qhi[t].w, kb1.z, kb1.w);
            }

            float2 bg0 = sb2[kg * 8 + tig];
            float2 bg1 = sb2[kg * 8 + 4 + tig];

            uint32_t pa[2][4];
            #pragma unroll
            for (int t = 0; t < 2; t++) {
                float p00 = ex2(c[t][0][0] + bg0.x), p01 = ex2(c[t][0][1] + bg0.y);
                float p02 = ex2(c[t][0][2] + bg0.x), p03 = ex2(c[t][0][3] + bg0.y);
                float p10 = ex2(c[t][1][0] + bg1.x), p11 = ex2(c[t][1][1] + bg1.y);
                float p12 = ex2(c[t][1][2] + bg1.x), p13 = ex2(c[t][1][3] + bg1.y);
                l[t][0] += (p00 + p01) + (p10 + p11);
                l[t][1] += (p02 + p03) + (p12 + p13);
                pa[t][0] = pack_h2(p00, p01);
                pa[t][1] = pack_h2(p02, p03);
                pa[t][2] = pack_h2(p10, p11);
                pa[t][3] = pack_h2(p12, p13);
            }

            const uint32_t* vb = &sv[kg * V_CHSTR + 8 * gid + 2 * tig];
            #pragma unroll
            for (int nc = 0; nc < 4; nc++) {
                uint2 vv = *(const uint2*)(vb + 64 * nc);
                mma16(o[0][nc], pa[0][0], pa[0][1], pa[0][2], pa[0][3], vv.x, vv.y);
                mma16(o[1][nc], pa[1][0], pa[1][1], pa[1][2], pa[1][3], vv.x, vv.y);
            }
        }
    }

    // ---- reduce l within groups; write partials ----
    const unsigned FULL = 0xffffffffu;
    #pragma unroll
    for (int t = 0; t < 2; t++) {
        float l0 = l[t][0], l1 = l[t][1];
        l0 += __shfl_xor_sync(FULL, l0, 1); l0 += __shfl_xor_sync(FULL, l0, 2);
        l1 += __shfl_xor_sync(FULL, l1, 1); l1 += __shfl_xor_sync(FULL, l1, 2);

        const int q0 = qbase + t * 16 + gid;
        const int q1 = q0 + 8;
        const int prow0 = ((h * S) + q0) * KSPLIT + kc;
        const int prow1 = ((h * S) + q1) * KSPLIT + kc;
        if (tig == 0) { g_pl[prow0] = l0; g_pl[prow1] = l1; }

        float2* po0 = (float2*)(g_po + (size_t)prow0 * D);
        float2* po1 = (float2*)(g_po + (size_t)prow1 * D);
        #pragma unroll
        for (int nc = 0; nc < 4; nc++) {
            po0[nc * 4 + tig] = make_float2(o[t][nc][0], o[t][nc][1]);
            po1[nc * 4 + tig] = make_float2(o[t][nc][2], o[t][nc][3]);
        }
    }
}

// ---------------- kernel 3: combine split-K + sum-pool over j ---------------
__global__ __launch_bounds__(128) void reduce_kernel(float* __restrict__ out) {
    const int i = blockIdx.x;
    const int h = blockIdx.y;
    const int tid = threadIdx.x;
    const int jg = tid >> 5;
    const int d  = tid & 31;

    __shared__ float sinvL[64];
    __shared__ float sacc[128];

    if (tid < 64) {
        int s = i * 64 + tid;
        int base = (h * S + s) * KSPLIT;
        float L = 0.0f;
        #pragma unroll
        for (int k = 0; k < KSPLIT; k++) L += g_pl[base + k];
        sinvL[tid] = 1.0f / L;
    }
    __syncthreads();

    float acc = 0.0f;
    #pragma unroll 4
    for (int jj = 0; jj < 16; jj++) {
        int j = jg * 16 + jj;
        int s = i * 64 + j;
        size_t base = ((size_t)(h * S + s) * KSPLIT) * D + d;
        float ov = 0.0f;
        #pragma unroll
        for (int k = 0; k < KSPLIT; k++) ov += g_po[base + (size_t)k * D];
        acc += ov * sinvL[j];
    }

    sacc[tid] = acc;
    __syncthreads();
    if (tid < 32) {
        float r = sacc[tid] + sacc[tid + 32] + sacc[tid + 64] + sacc[tid + 96];
        out[i * HD + h * 32 + tid] = r;
    }
}

// ---------------- launch ----------------------------------------------------
extern "C" void kernel_launch(void* const* d_in, const int* in_sizes, int n_in,
                              void* d_out, int out_size) {
    const float* x    = (const float*)d_in[0];
    const int*   mask = (const int*)  d_in[1];
    const float* Wq   = (const float*)d_in[2];
    const float* bq   = (const float*)d_in[3];
    const float* Wk   = (const float*)d_in[4];
    const float* bk   = (const float*)d_in[5];
    const float* Wv   = (const float*)d_in[6];
    const float* bv   = (const float*)d_in[7];
    float* out = (float*)d_out;

    cudaFuncSetAttribute(proj_kernel, cudaFuncAttributeMaxDynamicSharedMemorySize, PROJ_SMEM);
    proj_kernel<<<dim3(S / 128, 3), 256, PROJ_SMEM>>>(x, Wq, bq, Wk, bk, Wv, bv);
    attn_kernel<<<dim3(S / QT, H, KSPLIT), 256>>>(mask);
    reduce_kernel<<<dim3(64, H), 128>>>(out);
}